// round 3
// baseline (speedup 1.0000x reference)
#include <cuda_runtime.h>
#include <cuda_bf16.h>
#include <cstdint>

// DGCRM: after dead-code elimination, output = GRU cell over 16384 rows:
//   c = [h(64), x(2)]  (permuted combined vector, 66 wide)
//   z = sigmoid(c @ Wz + bz); r = sigmoid(c @ Wr + br)
//   cand = [r*h, x];  hc = tanh(cand @ Wc + bc)
//   out = z*h + (1-z)*hc
// Wz/Wr/Wc are folds of rnn_W pairs (the reference's GConv_RNN bug makes the
// graph-diffusion terms no-ops: concat([inp, .05*inp, .05*inp]) @ W).

#define CIN 66
#define HIDD 64
#define RPB 128
#define TPB 256

__device__ float g_Wf[3 * CIN * HIDD];
__device__ float g_Bf[3 * HIDD];

__device__ __forceinline__ unsigned long long pk2(float a, float b) {
    unsigned long long r;
    asm("mov.b64 %0, {%1, %2};" : "=l"(r) : "f"(a), "f"(b));
    return r;
}
__device__ __forceinline__ void upk2(unsigned long long v, float& a, float& b) {
    asm("mov.b64 {%0, %1}, %2;" : "=f"(a), "=f"(b) : "l"(v));
}
__device__ __forceinline__ void fma2(unsigned long long& d, unsigned long long a, unsigned long long b) {
    asm("fma.rn.f32x2 %0, %1, %2, %0;" : "+l"(d) : "l"(a), "l"(b));
}
__device__ __forceinline__ float fsig(float v) { return 1.f / (1.f + __expf(-v)); }
__device__ __forceinline__ float ftanh(float v) { return 1.f - 2.f / (__expf(2.f * v) + 1.f); }

// Fold rnn_W[6,198,64] -> 3 effective [66,64] matrices + biases.
// Weff[m] = sum_{i in {2m,2m+1}} (W[i][0:66] + 0.05*(W[i][66:132] + W[i][132:198]))
__global__ void fold_kernel(const float* __restrict__ W, const float* __restrict__ bvec) {
    int idx = blockIdx.x * blockDim.x + threadIdx.x;
    if (idx < 3 * CIN * HIDD) {
        int m = idx / (CIN * HIDD);
        int rem = idx - m * (CIN * HIDD);
        int k = rem / HIDD;
        int j = rem - k * HIDD;
        float s = 0.f;
#pragma unroll
        for (int t = 0; t < 2; ++t) {
            const float* base = W + (size_t)(2 * m + t) * 198 * HIDD + j;
            s += base[(size_t)k * HIDD]
               + 0.05f * (base[(size_t)(66 + k) * HIDD] + base[(size_t)(132 + k) * HIDD]);
        }
        g_Wf[idx] = s;
    }
    if (idx < 3 * HIDD) {
        int m = idx / HIDD, j = idx - m * HIDD;
        g_Bf[idx] = bvec[(2 * m) * HIDD + j] + bvec[(2 * m + 1) * HIDD + j];
    }
}

// Main fused GRU kernel. Block: 128 rows x 64 cols. Thread: 8 rows x 4 cols.
// smem: Wsm[3][66][64] (rows permuted to [h..,x]), Bsm[3][64], As[128][68].
__global__ void __launch_bounds__(TPB) dgcrm_main(
    const float* __restrict__ x, const float* __restrict__ h0, float* __restrict__ out)
{
    extern __shared__ float sm[];
    float* Wsm = sm;                        // 3*66*64 = 12672
    float* Bsm = Wsm + 3 * CIN * HIDD;      // 192
    float* As  = Bsm + 3 * HIDD;            // 128*68 = 8704

    const int tid = threadIdx.x;
    const int tx = tid & 15;                // col group (4 cols)
    const int ty = tid >> 4;                // row group (8 rows)
    const int rowbase = ty * 8;
    const int g0 = blockIdx.x * RPB;

    // Load + permute weights: smem row j corresponds to combined element
    // [h0..h63, x0, x1] -> source row (j<64 ? j+2 : j-64).
    for (int i = tid; i < 3 * CIN * 16; i += TPB) {
        int m = i / (CIN * 16);
        int rem = i - m * (CIN * 16);
        int j = rem >> 4;
        int c = rem & 15;
        int src = (j < HIDD) ? (j + 2) : (j - HIDD);
        float4 v = *(const float4*)(g_Wf + ((size_t)m * CIN + src) * HIDD + c * 4);
        *(float4*)(Wsm + ((size_t)m * CIN + j) * HIDD + c * 4) = v;
    }
    for (int i = tid; i < 3 * HIDD; i += TPB) Bsm[i] = g_Bf[i];

    // A tile: hidden into As[:,0:64] (coalesced float4), x into As[:,64:66].
    for (int i = tid; i < RPB * 16; i += TPB) {
        int r = i >> 4, c = i & 15;
        float4 v = *(const float4*)(h0 + (size_t)(g0 + r) * HIDD + c * 4);
        *(float4*)(As + r * 68 + c * 4) = v;
    }
    if (tid < RPB) {
        float2 v = *(const float2*)(x + (size_t)(g0 + tid) * 2);
        As[tid * 68 + 64] = v.x;
        As[tid * 68 + 65] = v.y;
    }
    __syncthreads();

    const float* Wz = Wsm;
    const float* Wr = Wsm + CIN * HIDD;
    const float* Wc = Wsm + 2 * CIN * HIDD;
    const float* arow = As + rowbase * 68;

    unsigned long long zacc[8][2], racc[8][2];
#pragma unroll
    for (int rr = 0; rr < 8; rr++) {
        zacc[rr][0] = 0ull; zacc[rr][1] = 0ull;
        racc[rr][0] = 0ull; racc[rr][1] = 0ull;
    }

    // ---- z / r GEMM phase (packed f32x2 FMAs) ----
#pragma unroll 2
    for (int j = 0; j < CIN; ++j) {
        float4 bz = *(const float4*)(Wz + j * HIDD + tx * 4);
        float4 br = *(const float4*)(Wr + j * HIDD + tx * 4);
        unsigned long long bz0 = pk2(bz.x, bz.y), bz1 = pk2(bz.z, bz.w);
        unsigned long long br0 = pk2(br.x, br.y), br1 = pk2(br.z, br.w);
        float a[8];
#pragma unroll
        for (int rr = 0; rr < 8; rr++) a[rr] = arow[rr * 68 + j];   // quarter-warp broadcast
#pragma unroll
        for (int rr = 0; rr < 8; rr++) {
            unsigned long long a2 = pk2(a[rr], a[rr]);
            fma2(zacc[rr][0], a2, bz0);
            fma2(zacc[rr][1], a2, bz1);
            fma2(racc[rr][0], a2, br0);
            fma2(racc[rr][1], a2, br1);
        }
    }
    __syncthreads();   // all As reads complete before in-place candidate update

    // ---- candidate: As[row][col] = sigmoid(r+br) * h, save h for epilogue ----
    float4 hsv[8];
    const float4 brb = *(const float4*)(Bsm + HIDD + tx * 4);
#pragma unroll
    for (int rr = 0; rr < 8; rr++) {
        float* ap = As + (rowbase + rr) * 68 + tx * 4;
        float4 h4 = *(const float4*)ap;
        hsv[rr] = h4;
        float r0, r1, r2, r3;
        upk2(racc[rr][0], r0, r1);
        upk2(racc[rr][1], r2, r3);
        float4 c4;
        c4.x = fsig(r0 + brb.x) * h4.x;
        c4.y = fsig(r1 + brb.y) * h4.y;
        c4.z = fsig(r2 + brb.z) * h4.z;
        c4.w = fsig(r3 + brb.w) * h4.w;
        *(float4*)ap = c4;
    }
    __syncthreads();

    // ---- hc GEMM phase ----
    unsigned long long cacc[8][2];
#pragma unroll
    for (int rr = 0; rr < 8; rr++) { cacc[rr][0] = 0ull; cacc[rr][1] = 0ull; }
#pragma unroll 2
    for (int j = 0; j < CIN; ++j) {
        float4 bc = *(const float4*)(Wc + j * HIDD + tx * 4);
        unsigned long long bc0 = pk2(bc.x, bc.y), bc1 = pk2(bc.z, bc.w);
        float a[8];
#pragma unroll
        for (int rr = 0; rr < 8; rr++) a[rr] = arow[rr * 68 + j];
#pragma unroll
        for (int rr = 0; rr < 8; rr++) {
            unsigned long long a2 = pk2(a[rr], a[rr]);
            fma2(cacc[rr][0], a2, bc0);
            fma2(cacc[rr][1], a2, bc1);
        }
    }

    // ---- epilogue: out = z*h + (1-z)*hc ----
    const float4 bzb = *(const float4*)(Bsm + tx * 4);
    const float4 bcb = *(const float4*)(Bsm + 2 * HIDD + tx * 4);
#pragma unroll
    for (int rr = 0; rr < 8; rr++) {
        float z0, z1, z2, z3, c0, c1, c2, c3;
        upk2(zacc[rr][0], z0, z1); upk2(zacc[rr][1], z2, z3);
        upk2(cacc[rr][0], c0, c1); upk2(cacc[rr][1], c2, c3);
        z0 = fsig(z0 + bzb.x); z1 = fsig(z1 + bzb.y);
        z2 = fsig(z2 + bzb.z); z3 = fsig(z3 + bzb.w);
        c0 = ftanh(c0 + bcb.x); c1 = ftanh(c1 + bcb.y);
        c2 = ftanh(c2 + bcb.z); c3 = ftanh(c3 + bcb.w);
        float4 o;
        o.x = z0 * hsv[rr].x + (1.f - z0) * c0;
        o.y = z1 * hsv[rr].y + (1.f - z1) * c1;
        o.z = z2 * hsv[rr].z + (1.f - z2) * c2;
        o.w = z3 * hsv[rr].w + (1.f - z3) * c3;
        *(float4*)(out + (size_t)(g0 + rowbase + rr) * HIDD + tx * 4) = o;
    }
}

static const int SMEM_BYTES = (3 * CIN * HIDD + 3 * HIDD + RPB * 68) * 4;  // 86272

extern "C" void kernel_launch(void* const* d_in, const int* in_sizes, int n_in,
                              void* d_out, int out_size) {
    (void)in_sizes; (void)n_in; (void)out_size;
    const float* x    = (const float*)d_in[0];    // [16,1024,2]
    const float* h0   = (const float*)d_in[1];    // [16,1024,64]
    const float* rnnW = (const float*)d_in[12];   // [6,198,64]
    const float* rnnb = (const float*)d_in[13];   // [6,64]
    float* out = (float*)d_out;                   // [16,1024,64]

    cudaFuncSetAttribute(dgcrm_main, cudaFuncAttributeMaxDynamicSharedMemorySize, SMEM_BYTES);

    fold_kernel<<<(3 * CIN * HIDD + 255) / 256, 256>>>(rnnW, rnnb);
    dgcrm_main<<<16384 / RPB, TPB, SMEM_BYTES>>>(x, h0, out);
}